// round 1
// baseline (speedup 1.0000x reference)
#include <cuda_runtime.h>

// DotProductAttention: O = softmax(mask(Q K^T / sqrt(D))) V
// B=64, S=1024, D=64, fp32. valid_lens[b] masks keys >= L with -1e6 (=> weight 0).
//
// Strategy: flash-attention style, one CTA per (batch, 64-query tile).
// 256 threads, each owns a 4x4 microtile of the 64x64 score tile and a 4x4
// microtile of the 64x64 output tile. Online softmax; skip key tiles >= L.

#define TS  64   // query/key tile size
#define DIM 64   // head dim

__global__ __launch_bounds__(256)
void attn_kernel(const float* __restrict__ Q, const float* __restrict__ K,
                 const float* __restrict__ V, const int* __restrict__ VL,
                 float* __restrict__ O, int S) {
    // 48 KB static smem total (fits default limit, 4 CTAs/SM)
    __shared__ float Qs[TS * DIM];   // transposed: Qs[d*TS + r], pre-scaled by 1/8
    __shared__ float KPs[TS * DIM];  // K transposed Ks[d*TS + c]; reused as P: Ps[k*TS + r]
    __shared__ float Vs[TS * DIM];   // row-major: Vs[k*DIM + d]

    const int b  = blockIdx.y;
    const int q0 = blockIdx.x * TS;
    const int tid = threadIdx.x;
    const int tx = tid & 15;   // output dim group / score col group
    const int ty = tid >> 4;   // row group

    const int L = VL[b];
    const int ntiles = (L + TS - 1) / TS;   // masked tiles contribute exactly 0 -> skip

    const float* Qg = Q + ((size_t)b * S + q0) * DIM;
    const float* Kg = K + (size_t)b * S * DIM;
    const float* Vg = V + (size_t)b * S * DIM;

    // Load Q tile transposed, folding in the 1/sqrt(64) scale.
    {
        const int r  = tid >> 2;          // 0..63
        const int c0 = (tid & 3) * 16;    // 0,16,32,48
        #pragma unroll
        for (int j = 0; j < 4; j++) {
            float4 f = *(const float4*)(Qg + r * DIM + c0 + 4 * j);
            const int c = c0 + 4 * j;
            Qs[(c + 0) * TS + r] = f.x * 0.125f;
            Qs[(c + 1) * TS + r] = f.y * 0.125f;
            Qs[(c + 2) * TS + r] = f.z * 0.125f;
            Qs[(c + 3) * TS + r] = f.w * 0.125f;
        }
    }

    float o[4][4] = {};
    float run_m[4], run_l[4];
    #pragma unroll
    for (int i = 0; i < 4; i++) { run_m[i] = -1e30f; run_l[i] = 0.0f; }

    for (int t = 0; t < ntiles; t++) {
        __syncthreads();   // previous iteration done reading KPs(P) and Vs
        // Load K tile transposed + V tile row-major.
        {
            const int r  = tid >> 2;
            const int c0 = (tid & 3) * 16;
            const float* krow = Kg + (size_t)(t * TS + r) * DIM + c0;
            #pragma unroll
            for (int j = 0; j < 4; j++) {
                float4 f = *(const float4*)(krow + 4 * j);
                const int c = c0 + 4 * j;
                KPs[(c + 0) * TS + r] = f.x;
                KPs[(c + 1) * TS + r] = f.y;
                KPs[(c + 2) * TS + r] = f.z;
                KPs[(c + 3) * TS + r] = f.w;
            }
            const float* vrow = Vg + (size_t)(t * TS + r) * DIM + c0;
            #pragma unroll
            for (int j = 0; j < 4; j++)
                *(float4*)(Vs + r * DIM + c0 + 4 * j) = *(const float4*)(vrow + 4 * j);
        }
        __syncthreads();

        // Score GEMM: s[i][j] = sum_k Qs[k][4ty+i] * Ks[k][4tx+j]
        float s[4][4] = {};
        #pragma unroll 8
        for (int k = 0; k < DIM; k++) {
            float a[4], bv[4];
            *(float4*)a  = *(const float4*)(Qs  + k * TS + 4 * ty);
            *(float4*)bv = *(const float4*)(KPs + k * TS + 4 * tx);
            #pragma unroll
            for (int i = 0; i < 4; i++)
                #pragma unroll
                for (int j = 0; j < 4; j++)
                    s[i][j] = fmaf(a[i], bv[j], s[i][j]);
        }

        // Mask partial last tile (same mask for every query row).
        #pragma unroll
        for (int j = 0; j < 4; j++) {
            if (t * TS + 4 * tx + j >= L) {
                #pragma unroll
                for (int i = 0; i < 4; i++) s[i][j] = -1e30f;
            }
        }

        // Online softmax per row; row spans 16 lanes (tx), reduce via shfl.
        #pragma unroll
        for (int i = 0; i < 4; i++) {
            float m = fmaxf(fmaxf(s[i][0], s[i][1]), fmaxf(s[i][2], s[i][3]));
            #pragma unroll
            for (int off = 8; off > 0; off >>= 1)
                m = fmaxf(m, __shfl_xor_sync(0xffffffffu, m, off));
            const float newm = fmaxf(run_m[i], m);
            const float corr = __expf(run_m[i] - newm);   // 0 on first tile
            run_m[i] = newm;
            float lsum = 0.0f;
            #pragma unroll
            for (int j = 0; j < 4; j++) {
                s[i][j] = __expf(s[i][j] - newm);          // masked -> exp(-1e30) = 0
                lsum += s[i][j];
            }
            #pragma unroll
            for (int off = 8; off > 0; off >>= 1)
                lsum += __shfl_xor_sync(0xffffffffu, lsum, off);
            run_l[i] = run_l[i] * corr + lsum;
            #pragma unroll
            for (int j = 0; j < 4; j++) o[i][j] *= corr;
        }

        __syncthreads();   // all score-GEMM reads of KPs done before P overwrite
        // Store P transposed: Ps[k][r]
        #pragma unroll
        for (int i = 0; i < 4; i++)
            #pragma unroll
            for (int j = 0; j < 4; j++)
                KPs[(4 * tx + j) * TS + 4 * ty + i] = s[i][j];
        __syncthreads();

        // PV GEMM: o[i][j] += sum_k Ps[k][4ty+i] * Vs[k][4tx+j]
        #pragma unroll 8
        for (int k = 0; k < TS; k++) {
            float p[4], v[4];
            *(float4*)p = *(const float4*)(KPs + k * TS + 4 * ty);
            *(float4*)v = *(const float4*)(Vs  + k * DIM + 4 * tx);
            #pragma unroll
            for (int i = 0; i < 4; i++)
                #pragma unroll
                for (int j = 0; j < 4; j++)
                    o[i][j] = fmaf(p[i], v[j], o[i][j]);
        }
    }

    // Normalize and write out. run_l >= 1 always (max is attained by a valid key).
    float* Og = O + ((size_t)b * S + q0) * DIM;
    #pragma unroll
    for (int i = 0; i < 4; i++) {
        const float inv = 1.0f / run_l[i];
        float4 st = make_float4(o[i][0] * inv, o[i][1] * inv,
                                o[i][2] * inv, o[i][3] * inv);
        *(float4*)(Og + (size_t)(4 * ty + i) * DIM + 4 * tx) = st;
    }
}

extern "C" void kernel_launch(void* const* d_in, const int* in_sizes, int n_in,
                              void* d_out, int out_size) {
    const float* Q  = (const float*)d_in[0];
    const float* K  = (const float*)d_in[1];
    const float* V  = (const float*)d_in[2];
    const int*   VL = (const int*)d_in[3];
    float* O = (float*)d_out;

    const int B = in_sizes[3];                  // valid_lens count
    const int S = in_sizes[0] / (B * DIM);      // 1024

    dim3 grid(S / TS, B);                       // (16, 64)
    attn_kernel<<<grid, 256>>>(Q, K, V, VL, O, S);
}

// round 2
// speedup vs baseline: 4.5600x; 4.5600x over previous
#include <cuda_runtime.h>
#include <cstdint>

// DotProductAttention via tensor cores (mma.sync m16n8k8 tf32).
// B=64, S=1024, D=64, fp32 in/out. Masked keys (>= valid_lens[b]) give weight 0
// exactly, so key tiles >= ceil(L/64) are skipped.
//
// CTA: 128 queries x 64 head-dim, 4 warps; warp w owns query rows [32w, 32w+32).
// Key tiles of 64. Softmax is fully in-warp (quad shfl). The P (C-layout) ->
// A-layout transpose for the PV GEMM is done with intra-quad shfl, no smem.

#define QS_STR 68           // Q smem row stride (== 4 mod 32 -> conflict-free A loads)
#define KB_BLK 584          // K k-block stride (== 8 mod 32)
#define VS_STR 72           // V smem row stride (== 8 mod 32 -> conflict-free B loads)
#define SMEM_FLOATS (128*QS_STR + 8*KB_BLK + 64*VS_STR)   // 8704+4672+4608 = 17984
#define SMEM_BYTES  (SMEM_FLOATS * 4)                      // 71936

__device__ __forceinline__ float tf32r(float x) {
    unsigned u;
    asm("cvt.rna.tf32.f32 %0, %1;" : "=r"(u) : "f"(x));
    return __uint_as_float(u);
}

__device__ __forceinline__ float ex2f(float x) {
    float r;
    asm("ex2.approx.f32 %0, %1;" : "=f"(r) : "f"(x));
    return r;
}

__device__ __forceinline__ void mma8(float c[4], const unsigned a[4],
                                     unsigned b0, unsigned b1) {
    asm("mma.sync.aligned.m16n8k8.row.col.f32.tf32.tf32.f32 "
        "{%0,%1,%2,%3}, {%4,%5,%6,%7}, {%8,%9}, {%0,%1,%2,%3};"
        : "+f"(c[0]), "+f"(c[1]), "+f"(c[2]), "+f"(c[3])
        : "r"(a[0]), "r"(a[1]), "r"(a[2]), "r"(a[3]), "r"(b0), "r"(b1));
}

__global__ __launch_bounds__(128)
void attn_tc(const float* __restrict__ Q, const float* __restrict__ K,
             const float* __restrict__ V, const int* __restrict__ VL,
             float* __restrict__ O, int S) {
    extern __shared__ float sm[];
    float* Qs = sm;                      // [128][QS_STR], holds Q * 0.125*log2e (tf32)
    float* Kb = sm + 128 * QS_STR;       // [8 kk][64 key][9]
    float* Vs = Kb + 8 * KB_BLK;         // [64 key][VS_STR]

    const int b   = blockIdx.y;
    const int q0  = blockIdx.x * 128;
    const int tid  = threadIdx.x;
    const int lane = tid & 31;
    const int w    = tid >> 5;
    const int g    = lane >> 2;   // groupID (row within fragment)
    const int q    = lane & 3;    // threadID in group
    const int wrow = w * 32;

    const int L = VL[b];
    const int ntiles = (L + 63) >> 6;

    const float* Qg = Q + ((size_t)b * S + q0) * 64;
    const float* Kg = K + (size_t)b * S * 64;
    const float* Vg = V + (size_t)b * S * 64;

    // log2-domain softmax: fold 1/sqrt(64) * log2(e) into Q.
    const float SCALE = 0.125f * 1.4426950408889634f;

    // Load Q tile (coalesced), tf32-rounded, pre-scaled.
    #pragma unroll
    for (int i = 0; i < 16; i++) {
        int idx = tid + 128 * i;
        int r = idx >> 4, c = (idx & 15) << 2;
        float4 f = *(const float4*)(Qg + r * 64 + c);
        float* d = Qs + r * QS_STR + c;
        d[0] = tf32r(f.x * SCALE); d[1] = tf32r(f.y * SCALE);
        d[2] = tf32r(f.z * SCALE); d[3] = tf32r(f.w * SCALE);
    }

    float o[2][8][4] = {};
    float run_m[2][2], run_l[2][2];
    #pragma unroll
    for (int mt = 0; mt < 2; mt++) {
        run_m[mt][0] = run_m[mt][1] = -1e30f;
        run_l[mt][0] = run_l[mt][1] = 0.0f;
    }

    const int  srcA = (lane & ~3) | (q >> 1);
    const int  srcC = srcA + 2;
    const bool odd  = q & 1;

    for (int t = 0; t < ntiles; t++) {
        __syncthreads();   // prev tile's QK/PV reads of Kb/Vs complete
        // Load K tile (k-blocked transposed-ish layout) + V tile (row-major).
        {
            const float* Kt = Kg + (size_t)t * 64 * 64;
            const float* Vt = Vg + (size_t)t * 64 * 64;
            #pragma unroll
            for (int i = 0; i < 8; i++) {
                int idx = tid + 128 * i;
                int key = idx >> 4, c = idx & 15, d0 = c << 2;
                float4 f = *(const float4*)(Kt + key * 64 + d0);
                float* kd = Kb + (c >> 1) * KB_BLK + key * 9 + ((c & 1) << 2);
                kd[0] = tf32r(f.x); kd[1] = tf32r(f.y);
                kd[2] = tf32r(f.z); kd[3] = tf32r(f.w);
                float4 v = *(const float4*)(Vt + key * 64 + d0);
                float4 vv = make_float4(tf32r(v.x), tf32r(v.y), tf32r(v.z), tf32r(v.w));
                *(float4*)(Vs + key * VS_STR + d0) = vv;
            }
        }
        __syncthreads();

        // ---- QK^T: S[128x64] in C fragments (log2-scaled scores) ----
        float s[2][8][4] = {};
        #pragma unroll
        for (int kk = 0; kk < 8; kk++) {
            unsigned a[2][4];
            #pragma unroll
            for (int mt = 0; mt < 2; mt++) {
                const float* qp = Qs + (wrow + mt * 16 + g) * QS_STR + kk * 8 + q;
                a[mt][0] = __float_as_uint(qp[0]);
                a[mt][1] = __float_as_uint(qp[8 * QS_STR]);
                a[mt][2] = __float_as_uint(qp[4]);
                a[mt][3] = __float_as_uint(qp[8 * QS_STR + 4]);
            }
            const float* kbase = Kb + kk * KB_BLK;
            #pragma unroll
            for (int nt = 0; nt < 8; nt++) {
                const float* kp = kbase + (nt * 8 + g) * 9 + q;
                unsigned b0 = __float_as_uint(kp[0]);
                unsigned b1 = __float_as_uint(kp[4]);
                mma8(s[0][nt], a[0], b0, b1);
                mma8(s[1][nt], a[1], b0, b1);
            }
        }

        // Mask partial last tile (cols >= L -> -1e30).
        if (t == ntiles - 1) {
            #pragma unroll
            for (int nt = 0; nt < 8; nt++) {
                int col = t * 64 + nt * 8 + 2 * q;
                if (col >= L) {
                    s[0][nt][0] = -1e30f; s[0][nt][2] = -1e30f;
                    s[1][nt][0] = -1e30f; s[1][nt][2] = -1e30f;
                }
                if (col + 1 >= L) {
                    s[0][nt][1] = -1e30f; s[0][nt][3] = -1e30f;
                    s[1][nt][1] = -1e30f; s[1][nt][3] = -1e30f;
                }
            }
        }

        // ---- Online softmax (base-2), fully in-warp ----
        #pragma unroll
        for (int mt = 0; mt < 2; mt++) {
            float mA = -1e30f, mB = -1e30f;
            #pragma unroll
            for (int nt = 0; nt < 8; nt++) {
                mA = fmaxf(mA, fmaxf(s[mt][nt][0], s[mt][nt][1]));
                mB = fmaxf(mB, fmaxf(s[mt][nt][2], s[mt][nt][3]));
            }
            mA = fmaxf(mA, __shfl_xor_sync(0xffffffffu, mA, 1));
            mA = fmaxf(mA, __shfl_xor_sync(0xffffffffu, mA, 2));
            mB = fmaxf(mB, __shfl_xor_sync(0xffffffffu, mB, 1));
            mB = fmaxf(mB, __shfl_xor_sync(0xffffffffu, mB, 2));
            float nmA = fmaxf(run_m[mt][0], mA);
            float nmB = fmaxf(run_m[mt][1], mB);
            float cA = ex2f(run_m[mt][0] - nmA);
            float cB = ex2f(run_m[mt][1] - nmB);
            run_m[mt][0] = nmA; run_m[mt][1] = nmB;
            float lA = 0.0f, lB = 0.0f;
            #pragma unroll
            for (int nt = 0; nt < 8; nt++) {
                s[mt][nt][0] = ex2f(s[mt][nt][0] - nmA);
                s[mt][nt][1] = ex2f(s[mt][nt][1] - nmA);
                s[mt][nt][2] = ex2f(s[mt][nt][2] - nmB);
                s[mt][nt][3] = ex2f(s[mt][nt][3] - nmB);
                lA += s[mt][nt][0] + s[mt][nt][1];
                lB += s[mt][nt][2] + s[mt][nt][3];
            }
            lA += __shfl_xor_sync(0xffffffffu, lA, 1);
            lA += __shfl_xor_sync(0xffffffffu, lA, 2);
            lB += __shfl_xor_sync(0xffffffffu, lB, 1);
            lB += __shfl_xor_sync(0xffffffffu, lB, 2);
            run_l[mt][0] = run_l[mt][0] * cA + lA;
            run_l[mt][1] = run_l[mt][1] * cB + lB;
            #pragma unroll
            for (int nt = 0; nt < 8; nt++) {
                o[mt][nt][0] *= cA; o[mt][nt][1] *= cA;
                o[mt][nt][2] *= cB; o[mt][nt][3] *= cB;
            }
        }

        // ---- PV: O += P * V. P's A-fragments built from C-fragments via
        //      intra-quad shfl (no smem roundtrip). ----
        #pragma unroll
        for (int kkl = 0; kkl < 8; kkl++) {
            unsigned a[2][4];
            #pragma unroll
            for (int mt = 0; mt < 2; mt++) {
                float x0 = __shfl_sync(0xffffffffu, s[mt][kkl][0], srcA);
                float x1 = __shfl_sync(0xffffffffu, s[mt][kkl][1], srcA);
                float z0 = __shfl_sync(0xffffffffu, s[mt][kkl][2], srcA);
                float z1 = __shfl_sync(0xffffffffu, s[mt][kkl][3], srcA);
                float y0 = __shfl_sync(0xffffffffu, s[mt][kkl][0], srcC);
                float y1 = __shfl_sync(0xffffffffu, s[mt][kkl][1], srcC);
                float w0 = __shfl_sync(0xffffffffu, s[mt][kkl][2], srcC);
                float w1 = __shfl_sync(0xffffffffu, s[mt][kkl][3], srcC);
                a[mt][0] = __float_as_uint(tf32r(odd ? x1 : x0));
                a[mt][1] = __float_as_uint(tf32r(odd ? z1 : z0));
                a[mt][2] = __float_as_uint(tf32r(odd ? y1 : y0));
                a[mt][3] = __float_as_uint(tf32r(odd ? w1 : w0));
            }
            const float* vb = Vs + kkl * 8 * VS_STR;
            #pragma unroll
            for (int nt = 0; nt < 8; nt++) {
                unsigned b0 = __float_as_uint(vb[q * VS_STR + nt * 8 + g]);
                unsigned b1 = __float_as_uint(vb[(q + 4) * VS_STR + nt * 8 + g]);
                mma8(o[0][nt], a[0], b0, b1);
                mma8(o[1][nt], a[1], b0, b1);
            }
        }
    }

    // ---- Epilogue: normalize and store ----
    float* Og = O + ((size_t)b * S + q0) * 64;
    #pragma unroll
    for (int mt = 0; mt < 2; mt++) {
        float iA = 1.0f / run_l[mt][0];
        float iB = 1.0f / run_l[mt][1];
        int rA = wrow + mt * 16 + g;
        #pragma unroll
        for (int nt = 0; nt < 8; nt++) {
            int c2 = nt * 8 + 2 * q;
            *(float2*)(Og + (size_t)rA * 64 + c2) =
                make_float2(o[mt][nt][0] * iA, o[mt][nt][1] * iA);
            *(float2*)(Og + (size_t)(rA + 8) * 64 + c2) =
                make_float2(o[mt][nt][2] * iB, o[mt][nt][3] * iB);
        }
    }
}

extern "C" void kernel_launch(void* const* d_in, const int* in_sizes, int n_in,
                              void* d_out, int out_size) {
    const float* Q  = (const float*)d_in[0];
    const float* K  = (const float*)d_in[1];
    const float* V  = (const float*)d_in[2];
    const int*   VL = (const int*)d_in[3];
    float* O = (float*)d_out;

    const int B = in_sizes[3];
    const int S = in_sizes[0] / (B * 64);   // 1024

    cudaFuncSetAttribute(attn_tc, cudaFuncAttributeMaxDynamicSharedMemorySize,
                         SMEM_BYTES);

    dim3 grid(S / 128, B);   // (8, 64)
    attn_tc<<<grid, 128, SMEM_BYTES>>>(Q, K, V, VL, O, S);
}

// round 3
// speedup vs baseline: 6.3239x; 1.3868x over previous
#include <cuda_runtime.h>
#include <cuda_fp16.h>
#include <cstdint>

// DotProductAttention via fp16 tensor cores (mma.sync m16n8k16, fp32 accum).
// B=64, S=1024, D=64, fp32 in/out. Keys >= valid_lens[b] have weight exactly 0,
// so key tiles >= ceil(L/64) are skipped.
//
// CTA: 256 threads (8 warps) x 128 queries; warp w owns query rows [16w,16w+16).
// Q fragments live in registers (loaded once). K and V tiles live in smem as
// half2 with stride-36 padding (conflict-free B-fragment loads). The P->A
// fragment conversion for PV is a pure register pack (fp16 layout identity).

#define H2STR 36   // half2 row stride: bank = 4g+q+const -> all 32 banks distinct

__device__ __forceinline__ float ex2f(float x) {
    float r;
    asm("ex2.approx.f32 %0, %1;" : "=f"(r) : "f"(x));
    return r;
}

__device__ __forceinline__ unsigned packh2(float a, float b) {
    __half2 h = __floats2half2_rn(a, b);
    return *(unsigned*)&h;
}

__device__ __forceinline__ void mma16(float c[4], const unsigned a[4],
                                      unsigned b0, unsigned b1) {
    asm("mma.sync.aligned.m16n8k16.row.col.f32.f16.f16.f32 "
        "{%0,%1,%2,%3}, {%4,%5,%6,%7}, {%8,%9}, {%0,%1,%2,%3};"
        : "+f"(c[0]), "+f"(c[1]), "+f"(c[2]), "+f"(c[3])
        : "r"(a[0]), "r"(a[1]), "r"(a[2]), "r"(a[3]), "r"(b0), "r"(b1));
}

__global__ __launch_bounds__(256, 2)
void attn_h16(const float* __restrict__ Q, const float* __restrict__ K,
              const float* __restrict__ V, const int* __restrict__ VL,
              float* __restrict__ O, int S) {
    // K tile: Kh2[key][dpair], row-major half2. V tile: Vp[dim][keypair],
    // transposed half2 (pairs along key). Both stride H2STR. 18.4 KB total.
    __shared__ __half2 Kh2[64 * H2STR];
    __shared__ __half2 Vp[64 * H2STR];

    const int b    = blockIdx.y;
    const int q0   = blockIdx.x * 128;
    const int tid  = threadIdx.x;
    const int lane = tid & 31;
    const int w    = tid >> 5;
    const int g    = lane >> 2;   // group id (fragment row)
    const int q    = lane & 3;    // thread in group
    const int wrow = w * 16;

    const int L = VL[b];
    const int ntiles = (L + 63) >> 6;

    const float* Qg = Q + ((size_t)b * S + q0) * 64;
    const float* Kg = K + (size_t)b * S * 64;
    const float* Vg = V + (size_t)b * S * 64;

    // log2-domain softmax: fold 1/sqrt(64) * log2(e) into Q.
    const float SCALE = 0.125f * 1.4426950408889634f;

    // ---- Q fragments in registers: qa[ks][0..3] for m16n8k16 A (16x16) ----
    unsigned qa[4][4];
    {
        const float* r0 = Qg + (size_t)(wrow + g) * 64;
        const float* r1 = r0 + 8 * 64;
        #pragma unroll
        for (int ks = 0; ks < 4; ks++) {
            const int c = ks * 16 + 2 * q;
            float2 f0 = *(const float2*)(r0 + c);
            float2 f1 = *(const float2*)(r1 + c);
            float2 f2 = *(const float2*)(r0 + c + 8);
            float2 f3 = *(const float2*)(r1 + c + 8);
            qa[ks][0] = packh2(f0.x * SCALE, f0.y * SCALE);
            qa[ks][1] = packh2(f1.x * SCALE, f1.y * SCALE);
            qa[ks][2] = packh2(f2.x * SCALE, f2.y * SCALE);
            qa[ks][3] = packh2(f3.x * SCALE, f3.y * SCALE);
        }
    }

    float o[8][4] = {};
    float run_m0 = -1e30f, run_m1 = -1e30f;
    float run_l0 = 0.0f,   run_l1 = 0.0f;

    for (int t = 0; t < ntiles; t++) {
        __syncthreads();   // previous tile's fragment reads complete
        // ---- Load K tile (row-major half2) + V tile (transposed half2) ----
        {
            const float* Kt = Kg + (size_t)t * 64 * 64;
            const float* Vt = Vg + (size_t)t * 64 * 64;
            __half* Vph = (__half*)Vp;
            #pragma unroll
            for (int i = 0; i < 4; i++) {
                const int idx = tid + 256 * i;
                const int row = idx >> 4;            // key
                const int c   = (idx & 15) << 2;     // dim base
                float4 kf = *(const float4*)(Kt + row * 64 + c);
                Kh2[row * H2STR + (c >> 1)]     = __floats2half2_rn(kf.x, kf.y);
                Kh2[row * H2STR + (c >> 1) + 1] = __floats2half2_rn(kf.z, kf.w);
                float4 vf = *(const float4*)(Vt + row * 64 + c);
                const int kp = row >> 1, kh = row & 1;
                Vph[((c + 0) * H2STR + kp) * 2 + kh] = __float2half_rn(vf.x);
                Vph[((c + 1) * H2STR + kp) * 2 + kh] = __float2half_rn(vf.y);
                Vph[((c + 2) * H2STR + kp) * 2 + kh] = __float2half_rn(vf.z);
                Vph[((c + 3) * H2STR + kp) * 2 + kh] = __float2half_rn(vf.w);
            }
        }
        __syncthreads();

        // ---- QK^T: s[nt][.] = C fragments of 16x64 scores (log2-scaled) ----
        float s[8][4] = {};
        #pragma unroll
        for (int ks = 0; ks < 4; ks++) {
            #pragma unroll
            for (int nt = 0; nt < 8; nt++) {
                const __half2* kp = Kh2 + (nt * 8 + g) * H2STR + ks * 8 + q;
                unsigned b0 = *(const unsigned*)(kp);
                unsigned b1 = *(const unsigned*)(kp + 4);
                mma16(s[nt], qa[ks], b0, b1);
            }
        }

        // ---- Mask partial last tile (cols >= L) ----
        if (t == ntiles - 1) {
            #pragma unroll
            for (int nt = 0; nt < 8; nt++) {
                const int col = t * 64 + nt * 8 + 2 * q;
                if (col >= L)     { s[nt][0] = -1e30f; s[nt][2] = -1e30f; }
                if (col + 1 >= L) { s[nt][1] = -1e30f; s[nt][3] = -1e30f; }
            }
        }

        // ---- Online softmax (base-2); rows g (c0,c1) and g+8 (c2,c3) ----
        {
            float mA = -1e30f, mB = -1e30f;
            #pragma unroll
            for (int nt = 0; nt < 8; nt++) {
                mA = fmaxf(mA, fmaxf(s[nt][0], s[nt][1]));
                mB = fmaxf(mB, fmaxf(s[nt][2], s[nt][3]));
            }
            mA = fmaxf(mA, __shfl_xor_sync(0xffffffffu, mA, 1));
            mA = fmaxf(mA, __shfl_xor_sync(0xffffffffu, mA, 2));
            mB = fmaxf(mB, __shfl_xor_sync(0xffffffffu, mB, 1));
            mB = fmaxf(mB, __shfl_xor_sync(0xffffffffu, mB, 2));
            const float nmA = fmaxf(run_m0, mA);
            const float nmB = fmaxf(run_m1, mB);
            const float cA = ex2f(run_m0 - nmA);
            const float cB = ex2f(run_m1 - nmB);
            run_m0 = nmA; run_m1 = nmB;
            float lA = 0.0f, lB = 0.0f;
            #pragma unroll
            for (int nt = 0; nt < 8; nt++) {
                s[nt][0] = ex2f(s[nt][0] - nmA);
                s[nt][1] = ex2f(s[nt][1] - nmA);
                s[nt][2] = ex2f(s[nt][2] - nmB);
                s[nt][3] = ex2f(s[nt][3] - nmB);
                lA += s[nt][0] + s[nt][1];
                lB += s[nt][2] + s[nt][3];
            }
            lA += __shfl_xor_sync(0xffffffffu, lA, 1);
            lA += __shfl_xor_sync(0xffffffffu, lA, 2);
            lB += __shfl_xor_sync(0xffffffffu, lB, 1);
            lB += __shfl_xor_sync(0xffffffffu, lB, 2);
            run_l0 = run_l0 * cA + lA;
            run_l1 = run_l1 * cB + lB;
            #pragma unroll
            for (int nt = 0; nt < 8; nt++) {
                o[nt][0] *= cA; o[nt][1] *= cA;
                o[nt][2] *= cB; o[nt][3] *= cB;
            }
        }

        // ---- PV: O += P * V. P A-fragments are direct register packs of the
        //      QK C fragments (fp16 layout identity, no shfl). ----
        #pragma unroll
        for (int ks = 0; ks < 4; ks++) {
            unsigned a[4];
            a[0] = packh2(s[2 * ks    ][0], s[2 * ks    ][1]);
            a[1] = packh2(s[2 * ks    ][2], s[2 * ks    ][3]);
            a[2] = packh2(s[2 * ks + 1][0], s[2 * ks + 1][1]);
            a[3] = packh2(s[2 * ks + 1][2], s[2 * ks + 1][3]);
            #pragma unroll
            for (int nt = 0; nt < 8; nt++) {
                const __half2* vp = Vp + (nt * 8 + g) * H2STR + ks * 8 + q;
                unsigned b0 = *(const unsigned*)(vp);
                unsigned b1 = *(const unsigned*)(vp + 4);
                mma16(o[nt], a, b0, b1);
            }
        }
    }

    // ---- Epilogue: normalize and store ----
    float* Og = O + ((size_t)b * S + q0) * 64;
    const float iA = 1.0f / run_l0;
    const float iB = 1.0f / run_l1;
    const int rA = wrow + g;
    #pragma unroll
    for (int nt = 0; nt < 8; nt++) {
        const int c2 = nt * 8 + 2 * q;
        *(float2*)(Og + (size_t)rA * 64 + c2) =
            make_float2(o[nt][0] * iA, o[nt][1] * iA);
        *(float2*)(Og + (size_t)(rA + 8) * 64 + c2) =
            make_float2(o[nt][2] * iB, o[nt][3] * iB);
    }
}

extern "C" void kernel_launch(void* const* d_in, const int* in_sizes, int n_in,
                              void* d_out, int out_size) {
    const float* Q  = (const float*)d_in[0];
    const float* K  = (const float*)d_in[1];
    const float* V  = (const float*)d_in[2];
    const int*   VL = (const int*)d_in[3];
    float* O = (float*)d_out;

    const int B = in_sizes[3];
    const int S = in_sizes[0] / (B * 64);   // 1024

    dim3 grid(S / 128, B);                  // (8, 64)
    attn_h16<<<grid, 256>>>(Q, K, V, VL, O, S);
}

// round 4
// speedup vs baseline: 7.5756x; 1.1979x over previous
#include <cuda_runtime.h>
#include <cuda_fp16.h>
#include <cstdint>

// DotProductAttention via fp16 tensor cores (mma.sync m16n8k16, fp32 accum).
// B=64, S=1024, D=64, fp32 in/out. Keys >= valid_lens[b] have weight exactly 0,
// so key tiles >= ceil(L/64) are skipped.
//
// R4: ldmatrix.x4 B-operand loads (K non-trans, V trans), both tiles stored
// row-major half [key][72], double-buffered smem -> 1 barrier per tile, global
// prefetch issued before the barrier.

#define HSTR 72                  // half stride per row (144 B)
#define TILE_H2 (64 * (HSTR/2))  // half2 elements per tile
#define TILEB 9216               // bytes per tile (64*144)

__device__ __forceinline__ float ex2f(float x) {
    float r; asm("ex2.approx.f32 %0, %1;" : "=f"(r) : "f"(x)); return r;
}
__device__ __forceinline__ unsigned packh2(float a, float b) {
    __half2 h = __floats2half2_rn(a, b); return *(unsigned*)&h;
}
__device__ __forceinline__ void mma16(float c[4], const unsigned a[4],
                                      unsigned b0, unsigned b1) {
    asm("mma.sync.aligned.m16n8k16.row.col.f32.f16.f16.f32 "
        "{%0,%1,%2,%3}, {%4,%5,%6,%7}, {%8,%9}, {%0,%1,%2,%3};"
        : "+f"(c[0]), "+f"(c[1]), "+f"(c[2]), "+f"(c[3])
        : "r"(a[0]), "r"(a[1]), "r"(a[2]), "r"(a[3]), "r"(b0), "r"(b1));
}
__device__ __forceinline__ void ldmx4(unsigned r[4], unsigned addr) {
    asm volatile("ldmatrix.sync.aligned.m8n8.x4.shared.b16 {%0,%1,%2,%3}, [%4];"
                 : "=r"(r[0]), "=r"(r[1]), "=r"(r[2]), "=r"(r[3]) : "r"(addr));
}
__device__ __forceinline__ void ldmx4t(unsigned r[4], unsigned addr) {
    asm volatile("ldmatrix.sync.aligned.m8n8.x4.trans.shared.b16 {%0,%1,%2,%3}, [%4];"
                 : "=r"(r[0]), "=r"(r[1]), "=r"(r[2]), "=r"(r[3]) : "r"(addr));
}

__global__ __launch_bounds__(256, 2)
void attn_h16(const float* __restrict__ Q, const float* __restrict__ K,
              const float* __restrict__ V, const int* __restrict__ VL,
              float* __restrict__ O, int S) {
    __shared__ __half2 KV[2][2][TILE_H2];   // [buf][K/V][row*36 + c2]  36.9 KB

    const int b    = blockIdx.y;
    const int q0   = blockIdx.x * 128;
    const int tid  = threadIdx.x;
    const int lane = tid & 31;
    const int w    = tid >> 5;
    const int g    = lane >> 2;
    const int q    = lane & 3;
    const int wrow = w * 16;

    const int L = VL[b];
    const int ntiles = (L + 63) >> 6;

    const float* Qg = Q + ((size_t)b * S + q0) * 64;
    const float* Kg = K + (size_t)b * S * 64;
    const float* Vg = V + (size_t)b * S * 64;

    const float SCALE = 0.125f * 1.4426950408889634f;   // 1/sqrt(64) * log2(e)

    // Q fragments in registers (16x64 A-tiles).
    unsigned qa[4][4];
    {
        const float* r0 = Qg + (size_t)(wrow + g) * 64;
        const float* r1 = r0 + 8 * 64;
        #pragma unroll
        for (int ks = 0; ks < 4; ks++) {
            const int c = ks * 16 + 2 * q;
            float2 f0 = *(const float2*)(r0 + c);
            float2 f1 = *(const float2*)(r1 + c);
            float2 f2 = *(const float2*)(r0 + c + 8);
            float2 f3 = *(const float2*)(r1 + c + 8);
            qa[ks][0] = packh2(f0.x * SCALE, f0.y * SCALE);
            qa[ks][1] = packh2(f1.x * SCALE, f1.y * SCALE);
            qa[ks][2] = packh2(f2.x * SCALE, f2.y * SCALE);
            qa[ks][3] = packh2(f3.x * SCALE, f3.y * SCALE);
        }
    }

    // Producer mapping: thread holds float4 column c4, rows (tid>>4)+16i.
    const int c4   = tid & 15;
    const int rw0  = tid >> 4;

    // ldmatrix lane base offsets (bytes).
    const unsigned kvbase = (unsigned)__cvta_generic_to_shared(&KV[0][0][0]);
    const int l8 = lane & 7;
    const unsigned qk_lo = (((lane >> 4) & 1) * 8 + l8) * 144 + ((lane >> 3) & 1) * 16;
    const unsigned pv_lo = (((lane >> 3) & 1) * 8 + l8) * 144 + ((lane >> 4) & 1) * 16;

    float o[8][4] = {};
    float run_m0 = -1e30f, run_m1 = -1e30f;
    float run_l0 = 0.0f,   run_l1 = 0.0f;

    // Prologue: load tile 0 into registers.
    float4 knx[4], vnx[4];
    #pragma unroll
    for (int i = 0; i < 4; i++) {
        const int row = rw0 + 16 * i;
        knx[i] = *(const float4*)(Kg + row * 64 + c4 * 4);
        vnx[i] = *(const float4*)(Vg + row * 64 + c4 * 4);
    }

    for (int t = 0; t < ntiles; t++) {
        const int buf = t & 1;
        // Store prefetched tile (convert fp32 -> fp16 at store).
        {
            __half2* Kb = KV[buf][0];
            __half2* Vb = KV[buf][1];
            #pragma unroll
            for (int i = 0; i < 4; i++) {
                const int off = (rw0 + 16 * i) * (HSTR / 2) + c4 * 2;
                uint2 kp, vp;
                kp.x = packh2(knx[i].x, knx[i].y); kp.y = packh2(knx[i].z, knx[i].w);
                vp.x = packh2(vnx[i].x, vnx[i].y); vp.y = packh2(vnx[i].z, vnx[i].w);
                *(uint2*)(Kb + off) = kp;
                *(uint2*)(Vb + off) = vp;
            }
        }
        // Issue next tile's global loads (latency hides under the MMAs).
        if (t + 1 < ntiles) {
            const float* Kt = Kg + (size_t)(t + 1) * 64 * 64;
            const float* Vt = Vg + (size_t)(t + 1) * 64 * 64;
            #pragma unroll
            for (int i = 0; i < 4; i++) {
                const int row = rw0 + 16 * i;
                knx[i] = *(const float4*)(Kt + row * 64 + c4 * 4);
                vnx[i] = *(const float4*)(Vt + row * 64 + c4 * 4);
            }
        }
        __syncthreads();   // tile ready; prev tile's other-buffer reads done

        const unsigned kbase = kvbase + buf * (2 * TILEB) + qk_lo;
        const unsigned vbase = kvbase + buf * (2 * TILEB) + TILEB + pv_lo;

        // ---- QK^T ----
        float s[8][4] = {};
        #pragma unroll
        for (int ks = 0; ks < 4; ks++) {
            unsigned kb[16];
            #pragma unroll
            for (int j = 0; j < 4; j++)
                ldmx4(kb + 4 * j, kbase + j * 2304 + ks * 32);
            #pragma unroll
            for (int nt = 0; nt < 8; nt++)
                mma16(s[nt], qa[ks], kb[2 * nt], kb[2 * nt + 1]);
        }

        // ---- Mask partial last tile ----
        if (t == ntiles - 1) {
            #pragma unroll
            for (int nt = 0; nt < 8; nt++) {
                const int col = t * 64 + nt * 8 + 2 * q;
                if (col >= L)     { s[nt][0] = -1e30f; s[nt][2] = -1e30f; }
                if (col + 1 >= L) { s[nt][1] = -1e30f; s[nt][3] = -1e30f; }
            }
        }

        // ---- Online softmax (base-2) ----
        {
            float mA = -1e30f, mB = -1e30f;
            #pragma unroll
            for (int nt = 0; nt < 8; nt++) {
                mA = fmaxf(mA, fmaxf(s[nt][0], s[nt][1]));
                mB = fmaxf(mB, fmaxf(s[nt][2], s[nt][3]));
            }
            mA = fmaxf(mA, __shfl_xor_sync(0xffffffffu, mA, 1));
            mA = fmaxf(mA, __shfl_xor_sync(0xffffffffu, mA, 2));
            mB = fmaxf(mB, __shfl_xor_sync(0xffffffffu, mB, 1));
            mB = fmaxf(mB, __shfl_xor_sync(0xffffffffu, mB, 2));
            const float nmA = fmaxf(run_m0, mA);
            const float nmB = fmaxf(run_m1, mB);
            const float cA = ex2f(run_m0 - nmA);
            const float cB = ex2f(run_m1 - nmB);
            run_m0 = nmA; run_m1 = nmB;
            float lA = 0.0f, lB = 0.0f;
            #pragma unroll
            for (int nt = 0; nt < 8; nt++) {
                s[nt][0] = ex2f(s[nt][0] - nmA);
                s[nt][1] = ex2f(s[nt][1] - nmA);
                s[nt][2] = ex2f(s[nt][2] - nmB);
                s[nt][3] = ex2f(s[nt][3] - nmB);
                lA += s[nt][0] + s[nt][1];
                lB += s[nt][2] + s[nt][3];
            }
            lA += __shfl_xor_sync(0xffffffffu, lA, 1);
            lA += __shfl_xor_sync(0xffffffffu, lA, 2);
            lB += __shfl_xor_sync(0xffffffffu, lB, 1);
            lB += __shfl_xor_sync(0xffffffffu, lB, 2);
            run_l0 = run_l0 * cA + lA;
            run_l1 = run_l1 * cB + lB;
            #pragma unroll
            for (int nt = 0; nt < 8; nt++) {
                o[nt][0] *= cA; o[nt][1] *= cA;
                o[nt][2] *= cB; o[nt][3] *= cB;
            }
        }

        // ---- PV (A = P register pack, B = trans ldmatrix of row-major V) ----
        #pragma unroll
        for (int ks = 0; ks < 4; ks++) {
            unsigned a[4];
            a[0] = packh2(s[2 * ks    ][0], s[2 * ks    ][1]);
            a[1] = packh2(s[2 * ks    ][2], s[2 * ks    ][3]);
            a[2] = packh2(s[2 * ks + 1][0], s[2 * ks + 1][1]);
            a[3] = packh2(s[2 * ks + 1][2], s[2 * ks + 1][3]);
            unsigned vb[16];
            #pragma unroll
            for (int j = 0; j < 4; j++)
                ldmx4t(vb + 4 * j, vbase + ks * 2304 + j * 32);
            #pragma unroll
            for (int nt = 0; nt < 8; nt++)
                mma16(o[nt], a, vb[2 * nt], vb[2 * nt + 1]);
        }
    }

    // ---- Epilogue ----
    float* Og = O + ((size_t)b * S + q0) * 64;
    const float iA = 1.0f / run_l0;
    const float iB = 1.0f / run_l1;
    const int rA = wrow + g;
    #pragma unroll
    for (int nt = 0; nt < 8; nt++) {
        const int c2 = nt * 8 + 2 * q;
        *(float2*)(Og + (size_t)rA * 64 + c2) =
            make_float2(o[nt][0] * iA, o[nt][1] * iA);
        *(float2*)(Og + (size_t)(rA + 8) * 64 + c2) =
            make_float2(o[nt][2] * iB, o[nt][3] * iB);
    }
}

extern "C" void kernel_launch(void* const* d_in, const int* in_sizes, int n_in,
                              void* d_out, int out_size) {
    const float* Q  = (const float*)d_in[0];
    const float* K  = (const float*)d_in[1];
    const float* V  = (const float*)d_in[2];
    const int*   VL = (const int*)d_in[3];
    float* O = (float*)d_out;

    const int B = in_sizes[3];
    const int S = in_sizes[0] / (B * 64);   // 1024

    dim3 grid(S / 128, B);                  // (8, 64)
    attn_h16<<<grid, 256>>>(Q, K, V, VL, O, S);
}

// round 5
// speedup vs baseline: 7.8488x; 1.0361x over previous
#include <cuda_runtime.h>
#include <cuda_fp16.h>
#include <cstdint>

// DotProductAttention, fp16 tensor cores (mma.sync m16n8k16, fp32 accum).
// B=64, S=1024, D=64, fp32 in/out. Keys >= valid_lens[b] have weight exactly 0,
// so key tiles >= ceil(L/64) are skipped.
//
// R5: prepass converts Q(scaled)/K/V to fp16 scratch once; main kernel streams
// K/V tiles via cp.async (LDGSTS) from fp16 -> no producer registers, no cvt,
// no STS, half the global bytes. ldmatrix.x4 B operands, one barrier per tile.

#define MAXE (64 * 1024 * 64)
__device__ __half Qh[MAXE];
__device__ __half Kh[MAXE];
__device__ __half Vh[MAXE];

#define HSTR 72        // half stride per smem row (144 B)
#define TILEH 4608     // halfs per tile (64*72)
#define TILEB 9216     // bytes per tile

__device__ __forceinline__ float ex2f(float x) {
    float r; asm("ex2.approx.f32 %0, %1;" : "=f"(r) : "f"(x)); return r;
}
__device__ __forceinline__ unsigned packh2(float a, float b) {
    __half2 h = __floats2half2_rn(a, b); return *(unsigned*)&h;
}
__device__ __forceinline__ void mma16(float c[4], const unsigned a[4],
                                      unsigned b0, unsigned b1) {
    asm("mma.sync.aligned.m16n8k16.row.col.f32.f16.f16.f32 "
        "{%0,%1,%2,%3}, {%4,%5,%6,%7}, {%8,%9}, {%0,%1,%2,%3};"
        : "+f"(c[0]), "+f"(c[1]), "+f"(c[2]), "+f"(c[3])
        : "r"(a[0]), "r"(a[1]), "r"(a[2]), "r"(a[3]), "r"(b0), "r"(b1));
}
__device__ __forceinline__ void ldmx4(unsigned r[4], unsigned addr) {
    asm volatile("ldmatrix.sync.aligned.m8n8.x4.shared.b16 {%0,%1,%2,%3}, [%4];"
                 : "=r"(r[0]), "=r"(r[1]), "=r"(r[2]), "=r"(r[3]) : "r"(addr));
}
__device__ __forceinline__ void ldmx4t(unsigned r[4], unsigned addr) {
    asm volatile("ldmatrix.sync.aligned.m8n8.x4.trans.shared.b16 {%0,%1,%2,%3}, [%4];"
                 : "=r"(r[0]), "=r"(r[1]), "=r"(r[2]), "=r"(r[3]) : "r"(addr));
}
__device__ __forceinline__ void cpa16(unsigned dst, const void* src) {
    asm volatile("cp.async.cg.shared.global [%0], [%1], 16;" :: "r"(dst), "l"(src));
}
__device__ __forceinline__ void cpa_commit() {
    asm volatile("cp.async.commit_group;");
}
__device__ __forceinline__ void cpa_wait0() {
    asm volatile("cp.async.wait_group 0;");
}

// ---- Prepass: fp32 -> fp16 (Q pre-scaled by 1/8 * log2(e)) ----
__global__ __launch_bounds__(256)
void cvt_kernel(const float4* __restrict__ q, const float4* __restrict__ k,
                const float4* __restrict__ v, int n4) {
    const float SCALE = 0.125f * 1.4426950408889634f;
    int i = blockIdx.x * 256 + threadIdx.x;
    if (i < n4) {
        float4 f = q[i];
        uint2 o;
        o.x = packh2(f.x * SCALE, f.y * SCALE);
        o.y = packh2(f.z * SCALE, f.w * SCALE);
        *(uint2*)(Qh + 4 * (size_t)i) = o;
        f = k[i];
        o.x = packh2(f.x, f.y); o.y = packh2(f.z, f.w);
        *(uint2*)(Kh + 4 * (size_t)i) = o;
        f = v[i];
        o.x = packh2(f.x, f.y); o.y = packh2(f.z, f.w);
        *(uint2*)(Vh + 4 * (size_t)i) = o;
    }
}

__global__ __launch_bounds__(256, 2)
void attn_h16(const int* __restrict__ VL, float* __restrict__ O, int S) {
    __shared__ __align__(16) __half KVs[2][2][TILEH];   // [buf][K/V] 36.9 KB

    const int b    = blockIdx.y;
    const int q0   = blockIdx.x * 128;
    const int tid  = threadIdx.x;
    const int lane = tid & 31;
    const int w    = tid >> 5;
    const int g    = lane >> 2;
    const int q    = lane & 3;
    const int wrow = w * 16;

    const int L = VL[b];
    const int ntiles = (L + 63) >> 6;

    // ---- Q fragments (pre-scaled fp16) straight from global ----
    unsigned qa[4][4];
    {
        const __half* r0 = Qh + ((size_t)b * S + q0 + wrow + g) * 64;
        const __half* r1 = r0 + 8 * 64;
        #pragma unroll
        for (int ks = 0; ks < 4; ks++) {
            const int c = ks * 16 + 2 * q;
            qa[ks][0] = *(const unsigned*)(r0 + c);
            qa[ks][1] = *(const unsigned*)(r1 + c);
            qa[ks][2] = *(const unsigned*)(r0 + c + 8);
            qa[ks][3] = *(const unsigned*)(r1 + c + 8);
        }
    }

    // Producer mapping: 512 16-byte chunks per tensor tile, 2 per thread.
    const int prow0 = tid >> 3;          // chunk row for i=0 (0..31)
    const int pc    = (tid & 7) * 16;    // byte column within row
    const __half* Kg = Kh + (size_t)b * S * 64;
    const __half* Vg = Vh + (size_t)b * S * 64;

    const unsigned kvb = (unsigned)__cvta_generic_to_shared(&KVs[0][0][0]);
    const int l8 = lane & 7;
    const unsigned qk_lo = (((lane >> 4) & 1) * 8 + l8) * 144 + ((lane >> 3) & 1) * 16;
    const unsigned pv_lo = (((lane >> 3) & 1) * 8 + l8) * 144 + ((lane >> 4) & 1) * 16;

    float o[8][4] = {};
    float run_m0 = -1e30f, run_m1 = -1e30f;
    float run_l0 = 0.0f,   run_l1 = 0.0f;

    // Prologue: cp.async tile 0 into buf 0.
    {
        const unsigned kd = kvb;
        const unsigned vd = kvb + TILEB;
        #pragma unroll
        for (int i = 0; i < 2; i++) {
            const int row = prow0 + 32 * i;
            cpa16(kd + row * 144 + pc, Kg + row * 64 + pc / 2);
            cpa16(vd + row * 144 + pc, Vg + row * 64 + pc / 2);
        }
        cpa_commit();
    }

    for (int t = 0; t < ntiles; t++) {
        const int buf = t & 1;
        cpa_wait0();
        __syncthreads();   // tile t resident; all reads of buf^1 (tile t-1) done

        // Issue tile t+1 into buf^1 (overlaps with tile-t compute).
        if (t + 1 < ntiles) {
            const __half* Kt = Kg + (size_t)(t + 1) * 64 * 64;
            const __half* Vt = Vg + (size_t)(t + 1) * 64 * 64;
            const unsigned kd = kvb + (buf ^ 1) * (2 * TILEB);
            const unsigned vd = kd + TILEB;
            #pragma unroll
            for (int i = 0; i < 2; i++) {
                const int row = prow0 + 32 * i;
                cpa16(kd + row * 144 + pc, Kt + row * 64 + pc / 2);
                cpa16(vd + row * 144 + pc, Vt + row * 64 + pc / 2);
            }
        }
        cpa_commit();

        const unsigned kbase = kvb + buf * (2 * TILEB) + qk_lo;
        const unsigned vbase = kvb + buf * (2 * TILEB) + TILEB + pv_lo;

        // ---- QK^T ----
        float s[8][4] = {};
        #pragma unroll
        for (int ks = 0; ks < 4; ks++) {
            unsigned kb[16];
            #pragma unroll
            for (int j = 0; j < 4; j++)
                ldmx4(kb + 4 * j, kbase + j * 2304 + ks * 32);
            #pragma unroll
            for (int nt = 0; nt < 8; nt++)
                mma16(s[nt], qa[ks], kb[2 * nt], kb[2 * nt + 1]);
        }

        // ---- Mask partial last tile ----
        if (t == ntiles - 1) {
            #pragma unroll
            for (int nt = 0; nt < 8; nt++) {
                const int col = t * 64 + nt * 8 + 2 * q;
                if (col >= L)     { s[nt][0] = -1e30f; s[nt][2] = -1e30f; }
                if (col + 1 >= L) { s[nt][1] = -1e30f; s[nt][3] = -1e30f; }
            }
        }

        // ---- Online softmax (base-2) ----
        {
            float mA = -1e30f, mB = -1e30f;
            #pragma unroll
            for (int nt = 0; nt < 8; nt++) {
                mA = fmaxf(mA, fmaxf(s[nt][0], s[nt][1]));
                mB = fmaxf(mB, fmaxf(s[nt][2], s[nt][3]));
            }
            mA = fmaxf(mA, __shfl_xor_sync(0xffffffffu, mA, 1));
            mA = fmaxf(mA, __shfl_xor_sync(0xffffffffu, mA, 2));
            mB = fmaxf(mB, __shfl_xor_sync(0xffffffffu, mB, 1));
            mB = fmaxf(mB, __shfl_xor_sync(0xffffffffu, mB, 2));
            const float nmA = fmaxf(run_m0, mA);
            const float nmB = fmaxf(run_m1, mB);
            const float cA = ex2f(run_m0 - nmA);
            const float cB = ex2f(run_m1 - nmB);
            run_m0 = nmA; run_m1 = nmB;
            float lA = 0.0f, lB = 0.0f;
            #pragma unroll
            for (int nt = 0; nt < 8; nt++) {
                s[nt][0] = ex2f(s[nt][0] - nmA);
                s[nt][1] = ex2f(s[nt][1] - nmA);
                s[nt][2] = ex2f(s[nt][2] - nmB);
                s[nt][3] = ex2f(s[nt][3] - nmB);
                lA += s[nt][0] + s[nt][1];
                lB += s[nt][2] + s[nt][3];
            }
            lA += __shfl_xor_sync(0xffffffffu, lA, 1);
            lA += __shfl_xor_sync(0xffffffffu, lA, 2);
            lB += __shfl_xor_sync(0xffffffffu, lB, 1);
            lB += __shfl_xor_sync(0xffffffffu, lB, 2);
            run_l0 = run_l0 * cA + lA;
            run_l1 = run_l1 * cB + lB;
            #pragma unroll
            for (int nt = 0; nt < 8; nt++) {
                o[nt][0] *= cA; o[nt][1] *= cA;
                o[nt][2] *= cB; o[nt][3] *= cB;
            }
        }

        // ---- PV (A = P register pack; B = trans ldmatrix of row-major V) ----
        #pragma unroll
        for (int ks = 0; ks < 4; ks++) {
            unsigned a[4];
            a[0] = packh2(s[2 * ks    ][0], s[2 * ks    ][1]);
            a[1] = packh2(s[2 * ks    ][2], s[2 * ks    ][3]);
            a[2] = packh2(s[2 * ks + 1][0], s[2 * ks + 1][1]);
            a[3] = packh2(s[2 * ks + 1][2], s[2 * ks + 1][3]);
            unsigned vb[16];
            #pragma unroll
            for (int j = 0; j < 4; j++)
                ldmx4t(vb + 4 * j, vbase + ks * 2304 + j * 32);
            #pragma unroll
            for (int nt = 0; nt < 8; nt++)
                mma16(o[nt], a, vb[2 * nt], vb[2 * nt + 1]);
        }
    }

    // ---- Epilogue ----
    float* Og = O + ((size_t)b * S + q0) * 64;
    const float iA = 1.0f / run_l0;
    const float iB = 1.0f / run_l1;
    const int rA = wrow + g;
    #pragma unroll
    for (int nt = 0; nt < 8; nt++) {
        const int c2 = nt * 8 + 2 * q;
        *(float2*)(Og + (size_t)rA * 64 + c2) =
            make_float2(o[nt][0] * iA, o[nt][1] * iA);
        *(float2*)(Og + (size_t)(rA + 8) * 64 + c2) =
            make_float2(o[nt][2] * iB, o[nt][3] * iB);
    }
}

extern "C" void kernel_launch(void* const* d_in, const int* in_sizes, int n_in,
                              void* d_out, int out_size) {
    const float* Q  = (const float*)d_in[0];
    const float* K  = (const float*)d_in[1];
    const float* V  = (const float*)d_in[2];
    const int*   VL = (const int*)d_in[3];
    float* O = (float*)d_out;

    const int B = in_sizes[3];
    const int S = in_sizes[0] / (B * 64);   // 1024
    const int n4 = in_sizes[0] / 4;

    cvt_kernel<<<(n4 + 255) / 256, 256>>>((const float4*)Q, (const float4*)K,
                                          (const float4*)V, n4);

    dim3 grid(S / 128, B);                  // (8, 64)
    attn_h16<<<grid, 256>>>(VL, O, S);
}

// round 6
// speedup vs baseline: 8.9797x; 1.1441x over previous
#include <cuda_runtime.h>
#include <cuda_fp16.h>
#include <cstdint>

// DotProductAttention, fp16 tensor cores (mma.sync m16n8k16, fp32 accum).
// B=64, S=1024, D=64, fp32 in/out. Keys >= valid_lens[b] have weight exactly 0;
// key tiles >= ceil(L/64) are skipped (also in the prepass).
//
// R6: ex2.approx.f16x2 softmax (half the MUFU ops), softmax denominator
// computed by an extra MMA against a constant all-ones B fragment (no shfl
// reduction for l), warp-vote skip of the o-rescale, prepass skips masked
// K/V tiles.

#define MAXE (64 * 1024 * 64)
__device__ __half Qh[MAXE];
__device__ __half Kh[MAXE];
__device__ __half Vh[MAXE];

#define TILEH 4608     // halfs per smem tile (64 rows * 72)
#define TILEB 9216     // bytes per tile
#define ONESH2 0x3C003C00u

__device__ __forceinline__ unsigned packh2(float a, float b) {
    __half2 h = __floats2half2_rn(a, b); return *(unsigned*)&h;
}
__device__ __forceinline__ unsigned ex2h2(unsigned x) {
    unsigned r; asm("ex2.approx.f16x2 %0, %1;" : "=r"(r) : "r"(x)); return r;
}
__device__ __forceinline__ float ex2f(float x) {
    float r; asm("ex2.approx.f32 %0, %1;" : "=f"(r) : "f"(x)); return r;
}
__device__ __forceinline__ void mma16(float c[4], const unsigned a[4],
                                      unsigned b0, unsigned b1) {
    asm("mma.sync.aligned.m16n8k16.row.col.f32.f16.f16.f32 "
        "{%0,%1,%2,%3}, {%4,%5,%6,%7}, {%8,%9}, {%0,%1,%2,%3};"
        : "+f"(c[0]), "+f"(c[1]), "+f"(c[2]), "+f"(c[3])
        : "r"(a[0]), "r"(a[1]), "r"(a[2]), "r"(a[3]), "r"(b0), "r"(b1));
}
__device__ __forceinline__ void ldmx4(unsigned r[4], unsigned addr) {
    asm volatile("ldmatrix.sync.aligned.m8n8.x4.shared.b16 {%0,%1,%2,%3}, [%4];"
                 : "=r"(r[0]), "=r"(r[1]), "=r"(r[2]), "=r"(r[3]) : "r"(addr));
}
__device__ __forceinline__ void ldmx4t(unsigned r[4], unsigned addr) {
    asm volatile("ldmatrix.sync.aligned.m8n8.x4.trans.shared.b16 {%0,%1,%2,%3}, [%4];"
                 : "=r"(r[0]), "=r"(r[1]), "=r"(r[2]), "=r"(r[3]) : "r"(addr));
}
__device__ __forceinline__ void cpa16(unsigned dst, const void* src) {
    asm volatile("cp.async.cg.shared.global [%0], [%1], 16;" :: "r"(dst), "l"(src));
}
__device__ __forceinline__ void cpa_commit() { asm volatile("cp.async.commit_group;"); }
__device__ __forceinline__ void cpa_wait0()  { asm volatile("cp.async.wait_group 0;"); }

// ---- Prepass: fp32 -> fp16; Q pre-scaled by 1/8*log2(e); K/V only for
//      unmasked tiles. grid = (S/64, B). ----
__global__ __launch_bounds__(256)
void cvt_kernel(const float4* __restrict__ q, const float4* __restrict__ k,
                const float4* __restrict__ v, const int* __restrict__ VL, int S) {
    const float SCALE = 0.125f * 1.4426950408889634f;
    const int t = blockIdx.x, b = blockIdx.y;
    const size_t base = ((size_t)b * S + t * 64) * 16;   // float4 index
    const int tid = threadIdx.x;
    #pragma unroll
    for (int i = 0; i < 4; i++) {
        const size_t idx = base + tid + 256 * i;
        float4 f = q[idx];
        uint2 o;
        o.x = packh2(f.x * SCALE, f.y * SCALE);
        o.y = packh2(f.z * SCALE, f.w * SCALE);
        *(uint2*)(Qh + idx * 4) = o;
    }
    if (t * 64 < VL[b]) {
        #pragma unroll
        for (int i = 0; i < 4; i++) {
            const size_t idx = base + tid + 256 * i;
            float4 f = k[idx];
            uint2 o;
            o.x = packh2(f.x, f.y); o.y = packh2(f.z, f.w);
            *(uint2*)(Kh + idx * 4) = o;
            f = v[idx];
            o.x = packh2(f.x, f.y); o.y = packh2(f.z, f.w);
            *(uint2*)(Vh + idx * 4) = o;
        }
    }
}

__global__ __launch_bounds__(256, 2)
void attn_h16(const int* __restrict__ VL, float* __restrict__ O, int S) {
    __shared__ __align__(16) __half KVs[2][2][TILEH];   // 36.9 KB

    const int b    = blockIdx.y;
    const int q0   = blockIdx.x * 128;
    const int tid  = threadIdx.x;
    const int lane = tid & 31;
    const int w    = tid >> 5;
    const int g    = lane >> 2;
    const int q    = lane & 3;
    const int wrow = w * 16;

    const int L = VL[b];
    const int ntiles = (L + 63) >> 6;

    // Q fragments (pre-scaled fp16) straight from global.
    unsigned qa[4][4];
    {
        const __half* r0 = Qh + ((size_t)b * S + q0 + wrow + g) * 64;
        const __half* r1 = r0 + 8 * 64;
        #pragma unroll
        for (int ks = 0; ks < 4; ks++) {
            const int c = ks * 16 + 2 * q;
            qa[ks][0] = *(const unsigned*)(r0 + c);
            qa[ks][1] = *(const unsigned*)(r1 + c);
            qa[ks][2] = *(const unsigned*)(r0 + c + 8);
            qa[ks][3] = *(const unsigned*)(r1 + c + 8);
        }
    }

    const int prow0 = tid >> 3;
    const int pc    = (tid & 7) * 16;
    const __half* Kg = Kh + (size_t)b * S * 64;
    const __half* Vg = Vh + (size_t)b * S * 64;

    const unsigned kvb = (unsigned)__cvta_generic_to_shared(&KVs[0][0][0]);
    const int l8 = lane & 7;
    const unsigned qk_lo = (((lane >> 4) & 1) * 8 + l8) * 144 + ((lane >> 3) & 1) * 16;
    const unsigned pv_lo = (((lane >> 3) & 1) * 8 + l8) * 144 + ((lane >> 4) & 1) * 16;

    // o[0..7]: output accum; o[8]: softmax denominator (P x ones).
    float o[9][4] = {};
    float run_m0 = -1e30f, run_m1 = -1e30f;

    // Prologue: cp.async tile 0 into buf 0.
    {
        #pragma unroll
        for (int i = 0; i < 2; i++) {
            const int row = prow0 + 32 * i;
            cpa16(kvb + row * 144 + pc, Kg + row * 64 + pc / 2);
            cpa16(kvb + TILEB + row * 144 + pc, Vg + row * 64 + pc / 2);
        }
        cpa_commit();
    }

    for (int t = 0; t < ntiles; t++) {
        const int buf = t & 1;
        cpa_wait0();
        __syncthreads();

        if (t + 1 < ntiles) {
            const __half* Kt = Kg + (size_t)(t + 1) * 64 * 64;
            const __half* Vt = Vg + (size_t)(t + 1) * 64 * 64;
            const unsigned kd = kvb + (buf ^ 1) * (2 * TILEB);
            #pragma unroll
            for (int i = 0; i < 2; i++) {
                const int row = prow0 + 32 * i;
                cpa16(kd + row * 144 + pc, Kt + row * 64 + pc / 2);
                cpa16(kd + TILEB + row * 144 + pc, Vt + row * 64 + pc / 2);
            }
        }
        cpa_commit();

        const unsigned kbase = kvb + buf * (2 * TILEB) + qk_lo;
        const unsigned vbase = kvb + buf * (2 * TILEB) + TILEB + pv_lo;

        // ---- QK^T ----
        float s[8][4] = {};
        #pragma unroll
        for (int ks = 0; ks < 4; ks++) {
            unsigned kb[16];
            #pragma unroll
            for (int j = 0; j < 4; j++)
                ldmx4(kb + 4 * j, kbase + j * 2304 + ks * 32);
            #pragma unroll
            for (int nt = 0; nt < 8; nt++)
                mma16(s[nt], qa[ks], kb[2 * nt], kb[2 * nt + 1]);
        }

        // ---- Mask partial last tile ----
        if (t == ntiles - 1) {
            #pragma unroll
            for (int nt = 0; nt < 8; nt++) {
                const int col = t * 64 + nt * 8 + 2 * q;
                if (col >= L)     { s[nt][0] = -1e30f; s[nt][2] = -1e30f; }
                if (col + 1 >= L) { s[nt][1] = -1e30f; s[nt][3] = -1e30f; }
            }
        }

        // ---- Online softmax (base-2), p in fp16 via ex2.f16x2 ----
        unsigned pp[8][2];
        {
            float mA = -1e30f, mB = -1e30f;
            #pragma unroll
            for (int nt = 0; nt < 8; nt++) {
                mA = fmaxf(mA, fmaxf(s[nt][0], s[nt][1]));
                mB = fmaxf(mB, fmaxf(s[nt][2], s[nt][3]));
            }
            mA = fmaxf(mA, __shfl_xor_sync(0xffffffffu, mA, 1));
            mA = fmaxf(mA, __shfl_xor_sync(0xffffffffu, mA, 2));
            mB = fmaxf(mB, __shfl_xor_sync(0xffffffffu, mB, 1));
            mB = fmaxf(mB, __shfl_xor_sync(0xffffffffu, mB, 2));
            const float nmA = fmaxf(run_m0, mA);
            const float nmB = fmaxf(run_m1, mB);
            const float cA = ex2f(run_m0 - nmA);
            const float cB = ex2f(run_m1 - nmB);
            run_m0 = nmA; run_m1 = nmB;
            #pragma unroll
            for (int nt = 0; nt < 8; nt++) {
                pp[nt][0] = ex2h2(packh2(s[nt][0] - nmA, s[nt][1] - nmA));
                pp[nt][1] = ex2h2(packh2(s[nt][2] - nmB, s[nt][3] - nmB));
            }
            // Rescale accumulators only if some row max changed.
            if (__any_sync(0xffffffffu, (cA != 1.0f) | (cB != 1.0f))) {
                #pragma unroll
                for (int nt = 0; nt < 9; nt++) {
                    o[nt][0] *= cA; o[nt][1] *= cA;
                    o[nt][2] *= cB; o[nt][3] *= cB;
                }
            }
        }

        // ---- PV (+ denominator via constant all-ones B fragment) ----
        #pragma unroll
        for (int ks = 0; ks < 4; ks++) {
            unsigned a[4] = { pp[2 * ks][0], pp[2 * ks][1],
                              pp[2 * ks + 1][0], pp[2 * ks + 1][1] };
            unsigned vb[16];
            #pragma unroll
            for (int j = 0; j < 4; j++)
                ldmx4t(vb + 4 * j, vbase + ks * 2304 + j * 32);
            #pragma unroll
            for (int nt = 0; nt < 8; nt++)
                mma16(o[nt], a, vb[2 * nt], vb[2 * nt + 1]);
            mma16(o[8], a, ONESH2, ONESH2);   // row-sum of P -> denominator
        }
    }

    // ---- Epilogue ----
    float* Og = O + ((size_t)b * S + q0) * 64;
    const float iA = 1.0f / o[8][0];
    const float iB = 1.0f / o[8][2];
    const int rA = wrow + g;
    #pragma unroll
    for (int nt = 0; nt < 8; nt++) {
        const int c2 = nt * 8 + 2 * q;
        *(float2*)(Og + (size_t)rA * 64 + c2) =
            make_float2(o[nt][0] * iA, o[nt][1] * iA);
        *(float2*)(Og + (size_t)(rA + 8) * 64 + c2) =
            make_float2(o[nt][2] * iB, o[nt][3] * iB);
    }
}

extern "C" void kernel_launch(void* const* d_in, const int* in_sizes, int n_in,
                              void* d_out, int out_size) {
    const float* Q  = (const float*)d_in[0];
    const float* K  = (const float*)d_in[1];
    const float* V  = (const float*)d_in[2];
    const int*   VL = (const int*)d_in[3];
    float* O = (float*)d_out;

    const int B = in_sizes[3];
    const int S = in_sizes[0] / (B * 64);   // 1024

    dim3 cgrid(S / 64, B);                  // (16, 64)
    cvt_kernel<<<cgrid, 256>>>((const float4*)Q, (const float4*)K,
                               (const float4*)V, VL, S);

    dim3 grid(S / 128, B);                  // (8, 64)
    attn_h16<<<grid, 256>>>(VL, O, S);
}

// round 7
// speedup vs baseline: 9.4880x; 1.0566x over previous
#include <cuda_runtime.h>
#include <cuda_fp16.h>
#include <cstdint>

// DotProductAttention, fp16 tensor cores (mma.sync m16n8k16, fp32 accum).
// B=64, S=1024, D=64, fp32 in/out. Keys >= valid_lens[b] have weight exactly 0;
// key tiles >= ceil(L/64) are skipped (also in the prepass).
//
// R7: 128-thread CTAs (64 queries) -> 4 independent pipelines/SM, half the
// convoy width, finer-grained grid. Softmax pp computed in two key-halves
// interleaved with the PV MMAs. Q converted in-kernel (prepass is K/V only).

#define MAXE (64 * 1024 * 64)
__device__ __half Kh[MAXE];
__device__ __half Vh[MAXE];

#define TILEH 4608     // halfs per smem tile (64 rows * 72)
#define TILEB 9216     // bytes per tile
#define ONESH2 0x3C003C00u

__device__ __forceinline__ unsigned packh2(float a, float b) {
    __half2 h = __floats2half2_rn(a, b); return *(unsigned*)&h;
}
__device__ __forceinline__ unsigned ex2h2(unsigned x) {
    unsigned r; asm("ex2.approx.f16x2 %0, %1;" : "=r"(r) : "r"(x)); return r;
}
__device__ __forceinline__ float ex2f(float x) {
    float r; asm("ex2.approx.f32 %0, %1;" : "=f"(r) : "f"(x)); return r;
}
__device__ __forceinline__ void mma16(float c[4], const unsigned a[4],
                                      unsigned b0, unsigned b1) {
    asm("mma.sync.aligned.m16n8k16.row.col.f32.f16.f16.f32 "
        "{%0,%1,%2,%3}, {%4,%5,%6,%7}, {%8,%9}, {%0,%1,%2,%3};"
        : "+f"(c[0]), "+f"(c[1]), "+f"(c[2]), "+f"(c[3])
        : "r"(a[0]), "r"(a[1]), "r"(a[2]), "r"(a[3]), "r"(b0), "r"(b1));
}
__device__ __forceinline__ void ldmx4(unsigned r[4], unsigned addr) {
    asm volatile("ldmatrix.sync.aligned.m8n8.x4.shared.b16 {%0,%1,%2,%3}, [%4];"
                 : "=r"(r[0]), "=r"(r[1]), "=r"(r[2]), "=r"(r[3]) : "r"(addr));
}
__device__ __forceinline__ void ldmx4t(unsigned r[4], unsigned addr) {
    asm volatile("ldmatrix.sync.aligned.m8n8.x4.trans.shared.b16 {%0,%1,%2,%3}, [%4];"
                 : "=r"(r[0]), "=r"(r[1]), "=r"(r[2]), "=r"(r[3]) : "r"(addr));
}
__device__ __forceinline__ void cpa16(unsigned dst, const void* src) {
    asm volatile("cp.async.cg.shared.global [%0], [%1], 16;" :: "r"(dst), "l"(src));
}
__device__ __forceinline__ void cpa_commit() { asm volatile("cp.async.commit_group;"); }
__device__ __forceinline__ void cpa_wait0()  { asm volatile("cp.async.wait_group 0;"); }

// ---- Prepass: K/V fp32 -> fp16, only unmasked tiles. grid = (S/64, B). ----
__global__ __launch_bounds__(256)
void cvt_kernel(const float4* __restrict__ k, const float4* __restrict__ v,
                const int* __restrict__ VL, int S) {
    const int t = blockIdx.x, b = blockIdx.y;
    if (t * 64 >= VL[b]) return;
    const size_t base = ((size_t)b * S + t * 64) * 16;   // float4 index
    const int tid = threadIdx.x;
    #pragma unroll
    for (int i = 0; i < 4; i++) {
        const size_t idx = base + tid + 256 * i;
        float4 f = k[idx];
        uint2 o;
        o.x = packh2(f.x, f.y); o.y = packh2(f.z, f.w);
        *(uint2*)(Kh + idx * 4) = o;
        f = v[idx];
        o.x = packh2(f.x, f.y); o.y = packh2(f.z, f.w);
        *(uint2*)(Vh + idx * 4) = o;
    }
}

__global__ __launch_bounds__(128, 4)
void attn_h16(const float* __restrict__ Qf, const int* __restrict__ VL,
              float* __restrict__ O, int S) {
    __shared__ __align__(16) __half KVs[2][2][TILEH];   // 36.9 KB

    const int b    = blockIdx.y;
    const int q0   = blockIdx.x * 64;
    const int tid  = threadIdx.x;
    const int lane = tid & 31;
    const int w    = tid >> 5;          // 0..3
    const int g    = lane >> 2;
    const int q    = lane & 3;
    const int wrow = w * 16;

    const int L = VL[b];
    const int ntiles = (L + 63) >> 6;

    const float SCALE = 0.125f * 1.4426950408889634f;   // 1/sqrt(64)*log2(e)

    // ---- Q fragments: fp32 global -> scaled fp16 regs (once) ----
    unsigned qa[4][4];
    {
        const float* r0 = Qf + ((size_t)b * S + q0 + wrow + g) * 64;
        const float* r1 = r0 + 8 * 64;
        #pragma unroll
        for (int ks = 0; ks < 4; ks++) {
            const int c = ks * 16 + 2 * q;
            float2 f0 = *(const float2*)(r0 + c);
            float2 f1 = *(const float2*)(r1 + c);
            float2 f2 = *(const float2*)(r0 + c + 8);
            float2 f3 = *(const float2*)(r1 + c + 8);
            qa[ks][0] = packh2(f0.x * SCALE, f0.y * SCALE);
            qa[ks][1] = packh2(f1.x * SCALE, f1.y * SCALE);
            qa[ks][2] = packh2(f2.x * SCALE, f2.y * SCALE);
            qa[ks][3] = packh2(f3.x * SCALE, f3.y * SCALE);
        }
    }

    // Producer: 512 16B chunks per tensor per tile; 128 threads x 4 each.
    const int prow0 = tid >> 3;          // 0..15
    const int pc    = (tid & 7) * 16;    // byte col
    const __half* Kg = Kh + (size_t)b * S * 64;
    const __half* Vg = Vh + (size_t)b * S * 64;

    const unsigned kvb = (unsigned)__cvta_generic_to_shared(&KVs[0][0][0]);
    const int l8 = lane & 7;
    const unsigned qk_lo = (((lane >> 4) & 1) * 8 + l8) * 144 + ((lane >> 3) & 1) * 16;
    const unsigned pv_lo = (((lane >> 3) & 1) * 8 + l8) * 144 + ((lane >> 4) & 1) * 16;

    // o[0..7]: output accum; o[8]: softmax denominator (P x ones).
    float o[9][4] = {};
    float run_m0 = -1e30f, run_m1 = -1e30f;

    // Prologue: cp.async tile 0 into buf 0.
    #pragma unroll
    for (int i = 0; i < 4; i++) {
        const int row = prow0 + 16 * i;
        cpa16(kvb + row * 144 + pc, Kg + row * 64 + pc / 2);
        cpa16(kvb + TILEB + row * 144 + pc, Vg + row * 64 + pc / 2);
    }
    cpa_commit();

    for (int t = 0; t < ntiles; t++) {
        const int buf = t & 1;
        cpa_wait0();
        __syncthreads();

        if (t + 1 < ntiles) {
            const __half* Kt = Kg + (size_t)(t + 1) * 64 * 64;
            const __half* Vt = Vg + (size_t)(t + 1) * 64 * 64;
            const unsigned kd = kvb + (buf ^ 1) * (2 * TILEB);
            #pragma unroll
            for (int i = 0; i < 4; i++) {
                const int row = prow0 + 16 * i;
                cpa16(kd + row * 144 + pc, Kt + row * 64 + pc / 2);
                cpa16(kd + TILEB + row * 144 + pc, Vt + row * 64 + pc / 2);
            }
        }
        cpa_commit();

        const unsigned kbase = kvb + buf * (2 * TILEB) + qk_lo;
        const unsigned vbase = kvb + buf * (2 * TILEB) + TILEB + pv_lo;

        // ---- QK^T ----
        float s[8][4] = {};
        #pragma unroll
        for (int ks = 0; ks < 4; ks++) {
            unsigned kb[16];
            #pragma unroll
            for (int j = 0; j < 4; j++)
                ldmx4(kb + 4 * j, kbase + j * 2304 + ks * 32);
            #pragma unroll
            for (int nt = 0; nt < 8; nt++)
                mma16(s[nt], qa[ks], kb[2 * nt], kb[2 * nt + 1]);
        }

        // ---- Mask partial last tile ----
        if (t == ntiles - 1) {
            #pragma unroll
            for (int nt = 0; nt < 8; nt++) {
                const int col = t * 64 + nt * 8 + 2 * q;
                if (col >= L)     { s[nt][0] = -1e30f; s[nt][2] = -1e30f; }
                if (col + 1 >= L) { s[nt][1] = -1e30f; s[nt][3] = -1e30f; }
            }
        }

        // ---- Online max + conditional rescale ----
        float nmA, nmB;
        {
            float mA = -1e30f, mB = -1e30f;
            #pragma unroll
            for (int nt = 0; nt < 8; nt++) {
                mA = fmaxf(mA, fmaxf(s[nt][0], s[nt][1]));
                mB = fmaxf(mB, fmaxf(s[nt][2], s[nt][3]));
            }
            mA = fmaxf(mA, __shfl_xor_sync(0xffffffffu, mA, 1));
            mA = fmaxf(mA, __shfl_xor_sync(0xffffffffu, mA, 2));
            mB = fmaxf(mB, __shfl_xor_sync(0xffffffffu, mB, 1));
            mB = fmaxf(mB, __shfl_xor_sync(0xffffffffu, mB, 2));
            nmA = fmaxf(run_m0, mA);
            nmB = fmaxf(run_m1, mB);
            const float cA = ex2f(run_m0 - nmA);
            const float cB = ex2f(run_m1 - nmB);
            run_m0 = nmA; run_m1 = nmB;
            if (__any_sync(0xffffffffu, (cA != 1.0f) | (cB != 1.0f))) {
                #pragma unroll
                for (int nt = 0; nt < 9; nt++) {
                    o[nt][0] *= cA; o[nt][1] *= cA;
                    o[nt][2] *= cB; o[nt][3] *= cB;
                }
            }
        }

        // ---- pp half 1 (keys 0..31), then PV ks 0..1 overlapped with
        //      pp half 2 (keys 32..63), then PV ks 2..3 ----
        unsigned pp[8][2];
        #pragma unroll
        for (int nt = 0; nt < 4; nt++) {
            pp[nt][0] = ex2h2(packh2(s[nt][0] - nmA, s[nt][1] - nmA));
            pp[nt][1] = ex2h2(packh2(s[nt][2] - nmB, s[nt][3] - nmB));
        }
        #pragma unroll
        for (int ks = 0; ks < 2; ks++) {
            unsigned a[4] = { pp[2 * ks][0], pp[2 * ks][1],
                              pp[2 * ks + 1][0], pp[2 * ks + 1][1] };
            unsigned vb[16];
            #pragma unroll
            for (int j = 0; j < 4; j++)
                ldmx4t(vb + 4 * j, vbase + ks * 2304 + j * 32);
            #pragma unroll
            for (int nt = 0; nt < 8; nt++)
                mma16(o[nt], a, vb[2 * nt], vb[2 * nt + 1]);
            mma16(o[8], a, ONESH2, ONESH2);
        }
        #pragma unroll
        for (int nt = 4; nt < 8; nt++) {
            pp[nt][0] = ex2h2(packh2(s[nt][0] - nmA, s[nt][1] - nmA));
            pp[nt][1] = ex2h2(packh2(s[nt][2] - nmB, s[nt][3] - nmB));
        }
        #pragma unroll
        for (int ks = 2; ks < 4; ks++) {
            unsigned a[4] = { pp[2 * ks][0], pp[2 * ks][1],
                              pp[2 * ks + 1][0], pp[2 * ks + 1][1] };
            unsigned vb[16];
            #pragma unroll
            for (int j = 0; j < 4; j++)
                ldmx4t(vb + 4 * j, vbase + ks * 2304 + j * 32);
            #pragma unroll
            for (int nt = 0; nt < 8; nt++)
                mma16(o[nt], a, vb[2 * nt], vb[2 * nt + 1]);
            mma16(o[8], a, ONESH2, ONESH2);
        }
    }

    // ---- Epilogue ----
    float* Og = O + ((size_t)b * S + q0) * 64;
    const float iA = 1.0f / o[8][0];
    const float iB = 1.0f / o[8][2];
    const int rA = wrow + g;
    #pragma unroll
    for (int nt = 0; nt < 8; nt++) {
        const int c2 = nt * 8 + 2 * q;
        *(float2*)(Og + (size_t)rA * 64 + c2) =
            make_float2(o[nt][0] * iA, o[nt][1] * iA);
        *(float2*)(Og + (size_t)(rA + 8) * 64 + c2) =
            make_float2(o[nt][2] * iB, o[nt][3] * iB);
    }
}

extern "C" void kernel_launch(void* const* d_in, const int* in_sizes, int n_in,
                              void* d_out, int out_size) {
    const float* Q  = (const float*)d_in[0];
    const float* K  = (const float*)d_in[1];
    const float* V  = (const float*)d_in[2];
    const int*   VL = (const int*)d_in[3];
    float* O = (float*)d_out;

    const int B = in_sizes[3];
    const int S = in_sizes[0] / (B * 64);   // 1024

    dim3 cgrid(S / 64, B);                  // (16, 64)
    cvt_kernel<<<cgrid, 256>>>((const float4*)K, (const float4*)V, VL, S);

    dim3 grid(S / 64, B);                   // (16, 64)
    attn_h16<<<grid, 128>>>(Q, VL, O, S);
}